// round 11
// baseline (speedup 1.0000x reference)
#include <cuda_runtime.h>
#include <cstdint>
#include <float.h>

// SOM2D winner-take-all, GB300 sm_103a — round 11.
// d = (||x||^2 + ||w||^2) - 2*x.w. R10: FFMA2 halved the math floor but
// occ=11% (4 warps/SM) left it latency-bound at 51% of floor. This round:
// 256 threads/CTA, 4x4 thread tile (distances bitwise identical to R10 —
// same f32x2 k-pair packing and reduction tree), __launch_bounds__(256,2)
// for 2 CTAs/SM. Smem unchanged: X 32KB + W double buffer 16KB = 48KB.

#define DD      128
#define TN      64      // samples per block
#define TM      64      // units per tile
#define CH      32      // k-chunk
#define THREADS 256

__device__ float g_wsq[8192];

__global__ void wsq_kernel(const float* __restrict__ W, int M)
{
    int m = blockIdx.x * blockDim.x + threadIdx.x;
    if (m < M) {
        const float* row = W + (size_t)m * DD;
        float s = 0.f;
#pragma unroll 8
        for (int k = 0; k < DD; k++) s = fmaf(row[k], row[k], s);
        g_wsq[m] = s;
    }
}

__device__ __forceinline__ void cp16(unsigned int dst, const float* src)
{
    asm volatile("cp.async.ca.shared.global [%0], [%1], 16;\n"
                 :: "r"(dst), "l"(src));
}
__device__ __forceinline__ void cp_commit()
{
    asm volatile("cp.async.commit_group;\n" ::: "memory");
}
template<int NN> __device__ __forceinline__ void cp_wait()
{
    asm volatile("cp.async.wait_group %0;\n" :: "n"(NN) : "memory");
}
__device__ __forceinline__ void ffma2(unsigned long long& acc,
                                      unsigned long long a,
                                      unsigned long long b)
{
    asm("fma.rn.f32x2 %0, %1, %2, %0;" : "+l"(acc) : "l"(a), "l"(b));
}

__global__ __launch_bounds__(THREADS, 2)
void som_kernel(const float* __restrict__ X, const float* __restrict__ W,
                const int* __restrict__ grid, float* __restrict__ out,
                int N, int M)
{
    __shared__ float X_s[TN * DD];       // 32768 B, quad-XOR swizzled
    __shared__ float W_s[2][TM * CH];    // 16384 B, quad-XOR swizzled

    const int tid = threadIdx.x;
    const int tx  = tid & 15;            // unit lane  (0..15)
    const int ty  = tid >> 4;            // sample lane (0..15)
    const int ty7 = ty & 7;
    const int txs = tx & 7;
    const int n0  = blockIdx.x * TN;

    const int iters = (M / TM) * (DD / CH);   // 64 * 4 = 256

    // ---- W chunk fill: 2x cp.async(16B) per thread, swizzled dst ----
    auto issue = [&](int it) {
        int t = it >> 2, c = it & 3, buf = it & 1;
        unsigned int dbase = (unsigned int)__cvta_generic_to_shared(&W_s[buf][0]);
#pragma unroll
        for (int p = 0; p < 2; p++) {
            int idx = tid + THREADS * p;
            int fr  = idx >> 3;          // row 0..63
            int fc  = idx & 7;           // quad 0..7
            int mr  = t * TM + fr; if (mr >= M) mr = M - 1;
            unsigned int dst = dbase +
                (unsigned int)((fr * CH + 4 * (fc ^ (fr & 7))) * 4);
            cp16(dst, W + (size_t)mr * DD + c * CH + 4 * fc);
        }
    };

    issue(0); cp_commit();

    // ---- X tile fill [TN x DD], float4, quad-XOR swizzle (q ^= r&7) ----
    for (int i = tid; i < TN * (DD / 4); i += THREADS) {
        int r = i >> 5, c4 = i & 31;
        float4 v = (n0 + r < N)
                 ? reinterpret_cast<const float4*>(X + (size_t)(n0 + r) * DD)[c4]
                 : make_float4(0.f, 0.f, 0.f, 0.f);
        *reinterpret_cast<float4*>(&X_s[r * DD + 4 * (c4 ^ (r & 7))]) = v;
    }
    __syncthreads();

    // ---- per-sample ||x||^2 for rows ty + 16*i ----
    float xq[4];
#pragma unroll
    for (int i = 0; i < 4; i++) {
        int r = ty + 16 * i;             // r & 7 == ty7
        float s = 0.f;
#pragma unroll
        for (int q = 0; q < 32; q++) {
            float4 v = *reinterpret_cast<const float4*>(&X_s[r * DD + 4 * (q ^ ty7)]);
            s = fmaf(v.x, v.x, s); s = fmaf(v.y, v.y, s);
            s = fmaf(v.z, v.z, s); s = fmaf(v.w, v.w, s);
        }
        xq[i] = s;
    }

    float bv[4];
    int   bi[4];
#pragma unroll
    for (int i = 0; i < 4; i++) { bv[i] = FLT_MAX; bi[i] = 0; }

    unsigned long long acc[4][4];
#pragma unroll
    for (int i = 0; i < 4; i++)
#pragma unroll
        for (int j = 0; j < 4; j++) acc[i][j] = 0ull;

    float wq[4] = {0.f, 0.f, 0.f, 0.f};

    for (int it = 0; it < iters; it++) {
        cp_wait<0>();                    // chunk 'it' landed (sole outstanding)
        __syncthreads();                 // visible to all; prev compute done
        if (it + 1 < iters) { issue(it + 1); cp_commit(); }

        const int t   = it >> 2;
        const int c   = it & 3;
        const int buf = it & 1;

        if (c == 0) {
#pragma unroll
            for (int j = 0; j < 4; j++) wq[j] = g_wsq[t * TM + tx + 16 * j];
        }

#pragma unroll
        for (int q = 0; q < CH / 4; q++) {
            ulonglong2 b[4];
#pragma unroll
            for (int j = 0; j < 4; j++) {
                int row = tx + 16 * j;   // row & 7 == txs
                b[j] = *reinterpret_cast<const ulonglong2*>(
                           &W_s[buf][row * CH + 4 * (q ^ txs)]);
            }
            const int qa = c * (CH / 4) + q;     // full k-quad 0..31
#pragma unroll
            for (int i = 0; i < 4; i++) {
                int row = ty + 16 * i;
                ulonglong2 a = *reinterpret_cast<const ulonglong2*>(
                                   &X_s[row * DD + 4 * (qa ^ ty7)]);
#pragma unroll
                for (int j = 0; j < 4; j++) {
                    ffma2(acc[i][j], a.x, b[j].x);
                    ffma2(acc[i][j], a.y, b[j].y);
                }
            }
        }

        if (c == 3) {                    // tile done: argmin update, reset acc
#pragma unroll
            for (int j = 0; j < 4; j++) {
                int g = t * TM + tx + 16 * j;
#pragma unroll
                for (int i = 0; i < 4; i++) {
                    float lo = __uint_as_float((unsigned int)(acc[i][j] & 0xffffffffull));
                    float hi = __uint_as_float((unsigned int)(acc[i][j] >> 32));
                    float cr = __fadd_rn(lo, hi);
                    float d  = __fsub_rn(__fadd_rn(xq[i], wq[j]),
                                         __fmul_rn(2.0f, cr));
                    if (d < bv[i]) { bv[i] = d; bi[i] = g; }  // ascending g -> first-min
                    acc[i][j] = 0ull;
                }
            }
        }
    }

    // ---- reduce across the 16 tx lanes (xor butterfly; o<16 stays in the
    //      same ty half of the warp, lane = (ty&1)*16 + tx) ----
#pragma unroll
    for (int i = 0; i < 4; i++) {
        float v  = bv[i];
        int   ix = bi[i];
#pragma unroll
        for (int o = 8; o; o >>= 1) {
            float v2 = __shfl_xor_sync(0xffffffffu, v,  o);
            int   i2 = __shfl_xor_sync(0xffffffffu, ix, o);
            if (v2 < v || (v2 == v && i2 < ix)) { v = v2; ix = i2; }
        }
        if (tx == 0) {
            int n = n0 + ty + 16 * i;
            if (n < N) {
                out[2 * n]     = (float)grid[2 * ix];
                out[2 * n + 1] = (float)grid[2 * ix + 1];
            }
        }
    }
}

extern "C" void kernel_launch(void* const* d_in, const int* in_sizes, int n_in,
                              void* d_out, int out_size)
{
    // Bind by element count: inputs = largest, grid = smallest, weights = rest.
    int ii = 0, ig = 0;
    for (int k = 1; k < n_in; k++) {
        if (in_sizes[k] > in_sizes[ii]) ii = k;
        if (in_sizes[k] < in_sizes[ig]) ig = k;
    }
    int iw = 0;
    for (int k = 0; k < n_in; k++) if (k != ii && k != ig) { iw = k; break; }

    const float* X    = (const float*)d_in[ii];
    const float* W    = (const float*)d_in[iw];
    const int*   grid = (const int*)d_in[ig];
    float*       out  = (float*)d_out;

    const int N = in_sizes[ii] / DD;     // 32768
    const int M = in_sizes[iw] / DD;     // 4096

    wsq_kernel<<<(M + 255) / 256, 256>>>(W, M);
    som_kernel<<<(N + TN - 1) / TN, THREADS>>>(X, W, grid, out, N, M);
}

// round 12
// speedup vs baseline: 1.1780x; 1.1780x over previous
#include <cuda_runtime.h>
#include <cstdint>
#include <float.h>

// SOM2D winner-take-all, GB300 sm_103a — round 12.
// d = (||x||^2 + ||w||^2) - 2*x.w. R10 (944us): 8x4 FFMA2 tile, latency-bound
// at 2 CTAs/SM (regs=180 caps the 3rd CTA). R11 (4x4 tile, more warps) showed
// occupancy bought with arithmetic-intensity loss regresses. R12 = R10 with
// __launch_bounds__(128,3): squeeze regs to <=170 for 3 CTAs/SM (12 warps).
// Distances bitwise identical to R10.

#define DD      128
#define TN      64      // samples per block
#define TM      64      // units per tile
#define CH      32      // k-chunk
#define THREADS 128

__device__ float g_wsq[8192];

__global__ void wsq_kernel(const float* __restrict__ W, int M)
{
    int m = blockIdx.x * blockDim.x + threadIdx.x;
    if (m < M) {
        const float* row = W + (size_t)m * DD;
        float s = 0.f;
#pragma unroll 8
        for (int k = 0; k < DD; k++) s = fmaf(row[k], row[k], s);
        g_wsq[m] = s;
    }
}

__device__ __forceinline__ void cp16(unsigned int dst, const float* src)
{
    asm volatile("cp.async.ca.shared.global [%0], [%1], 16;\n"
                 :: "r"(dst), "l"(src));
}
__device__ __forceinline__ void cp_commit()
{
    asm volatile("cp.async.commit_group;\n" ::: "memory");
}
template<int NN> __device__ __forceinline__ void cp_wait()
{
    asm volatile("cp.async.wait_group %0;\n" :: "n"(NN) : "memory");
}
__device__ __forceinline__ void ffma2(unsigned long long& acc,
                                      unsigned long long a,
                                      unsigned long long b)
{
    asm("fma.rn.f32x2 %0, %1, %2, %0;" : "+l"(acc) : "l"(a), "l"(b));
}

__global__ __launch_bounds__(THREADS, 3)
void som_kernel(const float* __restrict__ X, const float* __restrict__ W,
                const int* __restrict__ grid, float* __restrict__ out,
                int N, int M)
{
    __shared__ float X_s[TN * DD];       // 32768 B, quad-XOR swizzled
    __shared__ float W_s[2][TM * CH];    // 16384 B, quad-XOR swizzled

    const int tid = threadIdx.x;
    const int tx  = tid & 15;            // unit lane
    const int ty  = tid >> 4;            // sample lane (0..7)
    const int n0  = blockIdx.x * TN;

    const int iters = (M / TM) * (DD / CH);   // 64 * 4 = 256

    // ---- W chunk fill: 4x cp.async(16B) per thread, swizzled dst ----
    auto issue = [&](int it) {
        int t = it >> 2, c = it & 3, buf = it & 1;
        unsigned int dbase = (unsigned int)__cvta_generic_to_shared(&W_s[buf][0]);
#pragma unroll
        for (int p = 0; p < 4; p++) {
            int idx = tid + THREADS * p;
            int fr  = idx >> 3;          // row 0..63
            int fc  = idx & 7;           // quad 0..7
            int mr  = t * TM + fr; if (mr >= M) mr = M - 1;
            unsigned int dst = dbase +
                (unsigned int)((fr * CH + 4 * (fc ^ (fr & 7))) * 4);
            cp16(dst, W + (size_t)mr * DD + c * CH + 4 * fc);
        }
    };

    issue(0); cp_commit();

    // ---- X tile fill [TN x DD], float4, quad-XOR swizzle (q ^= r&7) ----
    for (int i = tid; i < TN * (DD / 4); i += THREADS) {
        int r = i >> 5, c4 = i & 31;
        float4 v = (n0 + r < N)
                 ? reinterpret_cast<const float4*>(X + (size_t)(n0 + r) * DD)[c4]
                 : make_float4(0.f, 0.f, 0.f, 0.f);
        *reinterpret_cast<float4*>(&X_s[r * DD + 4 * (c4 ^ (r & 7))]) = v;
    }
    __syncthreads();

    // ---- per-sample ||x||^2 (order argmin-invariant per sample) ----
    float xq[8];
#pragma unroll
    for (int i = 0; i < 8; i++) {
        int r = ty + 8 * i;              // r & 7 == ty
        float s = 0.f;
#pragma unroll
        for (int q = 0; q < 32; q++) {
            float4 v = *reinterpret_cast<const float4*>(&X_s[r * DD + 4 * (q ^ ty)]);
            s = fmaf(v.x, v.x, s); s = fmaf(v.y, v.y, s);
            s = fmaf(v.z, v.z, s); s = fmaf(v.w, v.w, s);
        }
        xq[i] = s;
    }

    float bv[8];
    int   bi[8];
#pragma unroll
    for (int i = 0; i < 8; i++) { bv[i] = FLT_MAX; bi[i] = 0; }

    unsigned long long acc[8][4];
#pragma unroll
    for (int i = 0; i < 8; i++)
#pragma unroll
        for (int j = 0; j < 4; j++) acc[i][j] = 0ull;

    float wq[4] = {0.f, 0.f, 0.f, 0.f};

    for (int it = 0; it < iters; it++) {
        cp_wait<0>();                    // chunk 'it' landed (sole outstanding)
        __syncthreads();                 // visible to all; prev compute done
        if (it + 1 < iters) { issue(it + 1); cp_commit(); }

        const int t   = it >> 2;
        const int c   = it & 3;
        const int buf = it & 1;

        if (c == 0) {
#pragma unroll
            for (int j = 0; j < 4; j++) wq[j] = g_wsq[t * TM + tx + 16 * j];
        }

        const int txs = tx & 7;
#pragma unroll
        for (int q = 0; q < CH / 4; q++) {
            ulonglong2 b[4];
#pragma unroll
            for (int j = 0; j < 4; j++) {
                int row = tx + 16 * j;   // row & 7 == txs
                b[j] = *reinterpret_cast<const ulonglong2*>(
                           &W_s[buf][row * CH + 4 * (q ^ txs)]);
            }
            const int qa = c * (CH / 4) + q;     // full k-quad 0..31
#pragma unroll
            for (int i = 0; i < 8; i++) {
                int row = ty + 8 * i;
                ulonglong2 a = *reinterpret_cast<const ulonglong2*>(
                                   &X_s[row * DD + 4 * (qa ^ ty)]);
#pragma unroll
                for (int j = 0; j < 4; j++) {
                    ffma2(acc[i][j], a.x, b[j].x);
                    ffma2(acc[i][j], a.y, b[j].y);
                }
            }
        }

        if (c == 3) {                    // tile done: argmin update, reset acc
#pragma unroll
            for (int j = 0; j < 4; j++) {
                int g = t * TM + tx + 16 * j;
#pragma unroll
                for (int i = 0; i < 8; i++) {
                    float lo = __uint_as_float((unsigned int)(acc[i][j] & 0xffffffffull));
                    float hi = __uint_as_float((unsigned int)(acc[i][j] >> 32));
                    float cr = __fadd_rn(lo, hi);
                    float d  = __fsub_rn(__fadd_rn(xq[i], wq[j]),
                                         __fmul_rn(2.0f, cr));
                    if (d < bv[i]) { bv[i] = d; bi[i] = g; }  // ascending g -> first-min
                    acc[i][j] = 0ull;
                }
            }
        }
    }

    // ---- reduce across the 16 tx lanes (xor butterfly, tie -> min index) ----
#pragma unroll
    for (int i = 0; i < 8; i++) {
        float v  = bv[i];
        int   ix = bi[i];
#pragma unroll
        for (int o = 8; o; o >>= 1) {
            float v2 = __shfl_xor_sync(0xffffffffu, v,  o);
            int   i2 = __shfl_xor_sync(0xffffffffu, ix, o);
            if (v2 < v || (v2 == v && i2 < ix)) { v = v2; ix = i2; }
        }
        if (tx == 0) {
            int n = n0 + ty + 8 * i;
            if (n < N) {
                out[2 * n]     = (float)grid[2 * ix];
                out[2 * n + 1] = (float)grid[2 * ix + 1];
            }
        }
    }
}

extern "C" void kernel_launch(void* const* d_in, const int* in_sizes, int n_in,
                              void* d_out, int out_size)
{
    // Bind by element count: inputs = largest, grid = smallest, weights = rest.
    int ii = 0, ig = 0;
    for (int k = 1; k < n_in; k++) {
        if (in_sizes[k] > in_sizes[ii]) ii = k;
        if (in_sizes[k] < in_sizes[ig]) ig = k;
    }
    int iw = 0;
    for (int k = 0; k < n_in; k++) if (k != ii && k != ig) { iw = k; break; }

    const float* X    = (const float*)d_in[ii];
    const float* W    = (const float*)d_in[iw];
    const int*   grid = (const int*)d_in[ig];
    float*       out  = (float*)d_out;

    const int N = in_sizes[ii] / DD;     // 32768
    const int M = in_sizes[iw] / DD;     // 4096

    wsq_kernel<<<(M + 255) / 256, 256>>>(W, M);
    som_kernel<<<(N + TN - 1) / TN, THREADS>>>(X, W, grid, out, N, M);
}